// round 2
// baseline (speedup 1.0000x reference)
#include <cuda_runtime.h>
#include <math.h>

#define NB 64
#define NS 512
#define NH 768
#define NC 50
#define NM 2000
#define NT (NB*NS)   // 32768

#define MCAP 2048    // per-mention active-token capacity (expect ~327)
#define UCAP 4096    // per-char utterance active capacity (expect ~655)
#define SCAP 512     // per-char mention-segment capacity (expect ~44)

#define NEGINF (__int_as_float(0xff800000))

// ---------------- scratch (device globals; no allocation) ----------------
__device__ float g_nts[NT];
__device__ float g_mts[NT];
__device__ float g_uts[NT];

__device__ float g_names_emb[(size_t)NC*NB*NH];  // 9.8 MB
__device__ float g_nscore[NC*NB];
__device__ float g_name_e[NC*NH];

__device__ float g_memb[(size_t)NM*NH];          // 6.1 MB
__device__ float g_mscore[NM];

__device__ float g_mention_e[NC*NH];
__device__ int   g_has_mention[NC];
__device__ float g_utt_e[NC*NH];
__device__ int   g_has_utt[NC];

// ---------------- block reductions (blockDim.x == 256) ----------------
__device__ __forceinline__ float blockReduceSum(float v) {
    __shared__ float sh[8];
    __shared__ float res;
    int lane = threadIdx.x & 31, wid = threadIdx.x >> 5;
    #pragma unroll
    for (int o = 16; o; o >>= 1) v += __shfl_xor_sync(0xffffffffu, v, o);
    if (lane == 0) sh[wid] = v;
    __syncthreads();
    if (threadIdx.x == 0) {
        float s = 0.f;
        #pragma unroll
        for (int i = 0; i < 8; i++) s += sh[i];
        res = s;
    }
    __syncthreads();
    return res;
}

__device__ __forceinline__ float blockReduceMax(float v) {
    __shared__ float sh[8];
    __shared__ float res;
    int lane = threadIdx.x & 31, wid = threadIdx.x >> 5;
    #pragma unroll
    for (int o = 16; o; o >>= 1) v = fmaxf(v, __shfl_xor_sync(0xffffffffu, v, o));
    if (lane == 0) sh[wid] = v;
    __syncthreads();
    if (threadIdx.x == 0) {
        float s = NEGINF;
        #pragma unroll
        for (int i = 0; i < 8; i++) s = fmaxf(s, sh[i]);
        res = s;
    }
    __syncthreads();
    return res;
}

// ---------------- K1: fused token projections (nts, mts, uts) ----------------
// one warp per token; single pass over story (100 MB)
__global__ void k_proj(const float* __restrict__ se,
                       const float* __restrict__ w_nt, const float* __restrict__ b_nt,
                       const float* __restrict__ w_mt, const float* __restrict__ b_mt,
                       const float* __restrict__ w_ut, const float* __restrict__ b_ut) {
    int warp = (blockIdx.x * blockDim.x + threadIdx.x) >> 5;
    int lane = threadIdx.x & 31;
    if (warp >= NT) return;
    const float4* row = (const float4*)(se + (size_t)warp * NH);
    const float4* wn = (const float4*)w_nt;
    const float4* wm = (const float4*)w_mt;
    const float4* wu = (const float4*)w_ut;
    float a = 0.f, b = 0.f, c = 0.f;
    #pragma unroll
    for (int i = 0; i < 6; i++) {
        float4 x = row[lane + 32 * i];
        float4 n = __ldg(&wn[lane + 32 * i]);
        float4 m = __ldg(&wm[lane + 32 * i]);
        float4 u = __ldg(&wu[lane + 32 * i]);
        a += x.x*n.x + x.y*n.y + x.z*n.z + x.w*n.w;
        b += x.x*m.x + x.y*m.y + x.z*m.z + x.w*m.w;
        c += x.x*u.x + x.y*u.y + x.z*u.z + x.w*u.w;
    }
    #pragma unroll
    for (int o = 16; o; o >>= 1) {
        a += __shfl_xor_sync(0xffffffffu, a, o);
        b += __shfl_xor_sync(0xffffffffu, b, o);
        c += __shfl_xor_sync(0xffffffffu, c, o);
    }
    if (lane == 0) {
        g_nts[warp] = a + __ldg(b_nt);
        g_mts[warp] = b + __ldg(b_mt);
        g_uts[warp] = c + __ldg(b_ut);
    }
}

// ---------------- K2: per-(char, block) name attention ----------------
__global__ void k_names(const float* __restrict__ se,
                        const float* __restrict__ nmask,
                        const float* __restrict__ w_name, const float* __restrict__ b_name) {
    int c = blockIdx.x / NB, b = blockIdx.x % NB;
    int tid = threadIdx.x;
    __shared__ int s_idx[NS];
    __shared__ float s_w[NS];
    __shared__ int s_cnt;
    if (tid == 0) s_cnt = 0;
    __syncthreads();

    float lmax = NEGINF;
    for (int s = tid; s < NS; s += 256) {
        float m = nmask[c * NS + s];
        if (m > -1e30f) {
            float sc = m + g_nts[b * NS + s];
            int p = atomicAdd(&s_cnt, 1);
            s_idx[p] = s; s_w[p] = sc;
            lmax = fmaxf(lmax, sc);
        }
    }
    lmax = blockReduceMax(lmax);          // barrier makes list writes visible
    int cnt = s_cnt;

    float lsum = 0.f;
    for (int i = tid; i < cnt; i += 256) {
        float e = expf(s_w[i] - lmax);
        s_w[i] = e; lsum += e;
    }
    float tot = blockReduceSum(lsum);
    float inv = 1.f / tot;

    const float* blk = se + (size_t)b * NS * NH;
    float a0 = 0.f, a1 = 0.f, a2 = 0.f;
    for (int i = 0; i < cnt; i++) {
        int s = s_idx[i];
        float w = s_w[i] * inv;
        const float* r = blk + (size_t)s * NH;
        a0 += w * r[tid];
        a1 += w * r[tid + 256];
        a2 += w * r[tid + 512];
    }
    size_t o = ((size_t)c * NB + b) * NH;
    g_names_emb[o + tid]       = a0;
    g_names_emb[o + tid + 256] = a1;
    g_names_emb[o + tid + 512] = a2;

    float d = a0 * __ldg(&w_name[tid]) + a1 * __ldg(&w_name[tid + 256]) + a2 * __ldg(&w_name[tid + 512]);
    d = blockReduceSum(d);
    if (tid == 0) g_nscore[c * NB + b] = d + __ldg(b_name);
}

// ---------------- K3: name_e = softmax over blocks ----------------
__global__ void k_name_e() {
    int c = blockIdx.x, tid = threadIdx.x;
    __shared__ float p[NB];
    if (tid == 0) {
        float mx = NEGINF;
        for (int b = 0; b < NB; b++) mx = fmaxf(mx, g_nscore[c * NB + b]);
        float s = 0.f;
        for (int b = 0; b < NB; b++) { float e = expf(g_nscore[c * NB + b] - mx); p[b] = e; s += e; }
        float inv = 1.f / s;
        for (int b = 0; b < NB; b++) p[b] *= inv;
    }
    __syncthreads();
    float a0 = 0.f, a1 = 0.f, a2 = 0.f;
    const float* base = g_names_emb + (size_t)c * NB * NH;
    for (int b = 0; b < NB; b++) {
        float w = p[b];
        const float* r = base + (size_t)b * NH;
        a0 += w * r[tid]; a1 += w * r[tid + 256]; a2 += w * r[tid + 512];
    }
    g_name_e[c * NH + tid]       = a0;
    g_name_e[c * NH + tid + 256] = a1;
    g_name_e[c * NH + tid + 512] = a2;
}

// ---------------- K4: fused mention compaction + softmax + gather + score ----------------
__global__ void k_mention(const float* __restrict__ mmask,
                          const float* __restrict__ se,
                          const float* __restrict__ w_men, const float* __restrict__ b_men) {
    int m = blockIdx.x, tid = threadIdx.x;
    __shared__ int s_idx[MCAP];
    __shared__ float s_sc[MCAP];
    __shared__ int s_cnt;
    if (tid == 0) s_cnt = 0;
    __syncthreads();

    const float4* row = (const float4*)(mmask + (size_t)m * NT);
    float lmax = NEGINF;
    for (int i = tid; i < NT / 4; i += 256) {
        float4 v = row[i];
        int t0 = i * 4;
        if (v.x > -1e30f) { int p = atomicAdd(&s_cnt, 1); if (p < MCAP) { float sc = v.x + g_mts[t0];     s_idx[p] = t0;     s_sc[p] = sc; lmax = fmaxf(lmax, sc); } }
        if (v.y > -1e30f) { int p = atomicAdd(&s_cnt, 1); if (p < MCAP) { float sc = v.y + g_mts[t0 + 1]; s_idx[p] = t0 + 1; s_sc[p] = sc; lmax = fmaxf(lmax, sc); } }
        if (v.z > -1e30f) { int p = atomicAdd(&s_cnt, 1); if (p < MCAP) { float sc = v.z + g_mts[t0 + 2]; s_idx[p] = t0 + 2; s_sc[p] = sc; lmax = fmaxf(lmax, sc); } }
        if (v.w > -1e30f) { int p = atomicAdd(&s_cnt, 1); if (p < MCAP) { float sc = v.w + g_mts[t0 + 3]; s_idx[p] = t0 + 3; s_sc[p] = sc; lmax = fmaxf(lmax, sc); } }
    }
    lmax = blockReduceMax(lmax);          // barrier: list complete & visible
    int cnt = min(s_cnt, MCAP);

    float lsum = 0.f;
    for (int i = tid; i < cnt; i += 256) {
        float e = expf(s_sc[i] - lmax);
        s_sc[i] = e; lsum += e;
    }
    float tot = blockReduceSum(lsum);     // barrier: s_sc exp values visible
    float inv = 1.f / tot;

    float a0 = 0.f, a1 = 0.f, a2 = 0.f;
    #pragma unroll 4
    for (int i = 0; i < cnt; i++) {
        int t = s_idx[i];
        float w = s_sc[i] * inv;
        const float* r = se + (size_t)t * NH;
        a0 += w * r[tid];
        a1 += w * r[tid + 256];
        a2 += w * r[tid + 512];
    }
    size_t o = (size_t)m * NH;
    g_memb[o + tid]       = a0;
    g_memb[o + tid + 256] = a1;
    g_memb[o + tid + 512] = a2;
    float d = a0 * __ldg(&w_men[tid]) + a1 * __ldg(&w_men[tid + 256]) + a2 * __ldg(&w_men[tid + 512]);
    d = blockReduceSum(d);
    if (tid == 0) g_mscore[m] = d + __ldg(b_men);
}

// ---------------- K5: utterance attention per char ----------------
__global__ void k_utt(const float* __restrict__ umask, const float* __restrict__ se) {
    int c = blockIdx.x, tid = threadIdx.x;
    __shared__ int s_idx[UCAP];
    __shared__ float s_sc[UCAP];
    __shared__ int s_cnt;
    if (tid == 0) s_cnt = 0;
    __syncthreads();

    const float4* row = (const float4*)(umask + (size_t)c * NT);
    float lmax = NEGINF;
    for (int i = tid; i < NT / 4; i += 256) {
        float4 v = row[i];
        int t0 = i * 4;
        if (v.x > -1e30f) { int p = atomicAdd(&s_cnt, 1); if (p < UCAP) { float sc = v.x + g_uts[t0];     s_idx[p] = t0;     s_sc[p] = sc; lmax = fmaxf(lmax, sc); } }
        if (v.y > -1e30f) { int p = atomicAdd(&s_cnt, 1); if (p < UCAP) { float sc = v.y + g_uts[t0 + 1]; s_idx[p] = t0 + 1; s_sc[p] = sc; lmax = fmaxf(lmax, sc); } }
        if (v.z > -1e30f) { int p = atomicAdd(&s_cnt, 1); if (p < UCAP) { float sc = v.z + g_uts[t0 + 2]; s_idx[p] = t0 + 2; s_sc[p] = sc; lmax = fmaxf(lmax, sc); } }
        if (v.w > -1e30f) { int p = atomicAdd(&s_cnt, 1); if (p < UCAP) { float sc = v.w + g_uts[t0 + 3]; s_idx[p] = t0 + 3; s_sc[p] = sc; lmax = fmaxf(lmax, sc); } }
    }
    lmax = blockReduceMax(lmax);
    int cnt = min(s_cnt, UCAP);

    if (cnt == 0) {  // no utterances: softmax is NaN -> nan_to_num -> zeros
        g_utt_e[c * NH + tid]       = 0.f;
        g_utt_e[c * NH + tid + 256] = 0.f;
        g_utt_e[c * NH + tid + 512] = 0.f;
        if (tid == 0) g_has_utt[c] = 0;
        return;
    }

    float lsum = 0.f;
    for (int i = tid; i < cnt; i += 256) {
        float e = expf(s_sc[i] - lmax);
        s_sc[i] = e; lsum += e;
    }
    float tot = blockReduceSum(lsum);
    float inv = 1.f / tot;

    float a0 = 0.f, a1 = 0.f, a2 = 0.f;
    for (int i = 0; i < cnt; i++) {
        int t = s_idx[i];
        float w = s_sc[i] * inv;
        const float* r = se + (size_t)t * NH;
        a0 += w * r[tid];
        a1 += w * r[tid + 256];
        a2 += w * r[tid + 512];
    }
    g_utt_e[c * NH + tid]       = a0;
    g_utt_e[c * NH + tid + 256] = a1;
    g_utt_e[c * NH + tid + 512] = a2;
    if (tid == 0) g_has_utt[c] = 1;
}

// ---------------- K6: segment softmax over mentions -> mention_e ----------------
__global__ void k_mention_e(const int* __restrict__ mids) {
    int c = blockIdx.x, tid = threadIdx.x;
    __shared__ int s_m[SCAP];
    __shared__ float s_w[SCAP];
    __shared__ int s_cnt;
    if (tid == 0) s_cnt = 0;
    __syncthreads();

    float lmax = NEGINF;
    for (int m = tid; m < NM; m += 256) {
        if (mids[m] == c) {
            int p = atomicAdd(&s_cnt, 1);
            if (p < SCAP) {
                float sc = g_mscore[m];
                s_m[p] = m; s_w[p] = sc;
                lmax = fmaxf(lmax, sc);
            }
        }
    }
    lmax = blockReduceMax(lmax);
    int cnt = min(s_cnt, SCAP);

    if (cnt == 0) {  // segment_sum over empty segment -> zeros
        g_mention_e[c * NH + tid]       = 0.f;
        g_mention_e[c * NH + tid + 256] = 0.f;
        g_mention_e[c * NH + tid + 512] = 0.f;
        if (tid == 0) g_has_mention[c] = 0;
        return;
    }

    float lsum = 0.f;
    for (int i = tid; i < cnt; i += 256) {
        float e = expf(s_w[i] - lmax);
        s_w[i] = e; lsum += e;
    }
    float tot = blockReduceSum(lsum);
    float inv = 1.f / tot;

    float a0 = 0.f, a1 = 0.f, a2 = 0.f;
    for (int i = 0; i < cnt; i++) {
        float w = s_w[i] * inv;
        const float* r = g_memb + (size_t)s_m[i] * NH;
        a0 += w * r[tid];
        a1 += w * r[tid + 256];
        a2 += w * r[tid + 512];
    }
    g_mention_e[c * NH + tid]       = a0;
    g_mention_e[c * NH + tid + 256] = a1;
    g_mention_e[c * NH + tid + 512] = a2;
    if (tid == 0) g_has_mention[c] = 1;
}

// ---------------- K7: final 3-way combine ----------------
__global__ void k_combine(const float* __restrict__ w_comb, const float* __restrict__ b_comb,
                          float* __restrict__ out) {
    int c = blockIdx.x, tid = threadIdx.x;
    float wc0 = __ldg(&w_comb[tid]), wc1 = __ldg(&w_comb[tid + 256]), wc2 = __ldg(&w_comb[tid + 512]);
    float n0 = g_name_e[c * NH + tid], n1 = g_name_e[c * NH + tid + 256], n2 = g_name_e[c * NH + tid + 512];
    float m0 = g_mention_e[c * NH + tid], m1 = g_mention_e[c * NH + tid + 256], m2 = g_mention_e[c * NH + tid + 512];
    float u0 = g_utt_e[c * NH + tid], u1 = g_utt_e[c * NH + tid + 256], u2 = g_utt_e[c * NH + tid + 512];

    float dn = blockReduceSum(n0 * wc0 + n1 * wc1 + n2 * wc2);
    float dm = blockReduceSum(m0 * wc0 + m1 * wc1 + m2 * wc2);
    float du = blockReduceSum(u0 * wc0 + u1 * wc1 + u2 * wc2);

    __shared__ float attn[3];
    if (tid == 0) {
        float bc = __ldg(b_comb);
        float s0 = dn + bc;
        float s1 = g_has_mention[c] ? (dm + bc) : NEGINF;
        float s2 = g_has_utt[c]     ? (du + bc) : NEGINF;
        float mx = fmaxf(s0, fmaxf(s1, s2));
        float e0 = expf(s0 - mx);
        float e1 = (s1 > -1e30f) ? expf(s1 - mx) : 0.f;
        float e2 = (s2 > -1e30f) ? expf(s2 - mx) : 0.f;
        float inv = 1.f / (e0 + e1 + e2);
        attn[0] = e0 * inv; attn[1] = e1 * inv; attn[2] = e2 * inv;
    }
    __syncthreads();
    float A0 = attn[0], A1 = attn[1], A2 = attn[2];
    out[c * NH + tid]       = A0 * n0 + A1 * m0 + A2 * u0;
    out[c * NH + tid + 256] = A0 * n1 + A1 * m1 + A2 * u1;
    out[c * NH + tid + 512] = A0 * n2 + A1 * m2 + A2 * u2;
}

// ---------------- launch ----------------
extern "C" void kernel_launch(void* const* d_in, const int* in_sizes, int n_in,
                              void* d_out, int out_size) {
    const float* se        = (const float*)d_in[0];
    const float* nmask     = (const float*)d_in[1];
    const float* umask     = (const float*)d_in[2];
    const float* mmask     = (const float*)d_in[3];
    const int*   mids      = (const int*)  d_in[4];
    const float* w_name_tok = (const float*)d_in[5];
    const float* b_name_tok = (const float*)d_in[6];
    const float* w_name     = (const float*)d_in[7];
    const float* b_name     = (const float*)d_in[8];
    const float* w_men_tok  = (const float*)d_in[9];
    const float* b_men_tok  = (const float*)d_in[10];
    const float* w_men      = (const float*)d_in[11];
    const float* b_men      = (const float*)d_in[12];
    const float* w_utt      = (const float*)d_in[13];
    const float* b_utt      = (const float*)d_in[14];
    const float* w_comb     = (const float*)d_in[15];
    const float* b_comb     = (const float*)d_in[16];
    float* out = (float*)d_out;

    k_proj<<<NT / 8, 256>>>(se, w_name_tok, b_name_tok, w_men_tok, b_men_tok, w_utt, b_utt);
    k_names<<<NC * NB, 256>>>(se, nmask, w_name, b_name);
    k_name_e<<<NC, 256>>>();
    k_mention<<<NM, 256>>>(mmask, se, w_men, b_men);
    k_utt<<<NC, 256>>>(umask, se);
    k_mention_e<<<NC, 256>>>(mids);
    k_combine<<<NC, 256>>>(w_comb, b_comb, out);
}

// round 3
// speedup vs baseline: 1.2851x; 1.2851x over previous
#include <cuda_runtime.h>
#include <math.h>

#define NB 64
#define NS 512
#define NH 768
#define NC 50
#define NM 2000
#define NT (NB*NS)   // 32768

#define MCAP 2048    // per-mention active-token capacity (expect ~327)
#define UCAP 4096    // per-char utterance active capacity (expect ~655)
#define SCAP 512     // per-char mention-segment capacity (expect ~44)

#define NEGINF (__int_as_float(0xff800000))

// ---------------- scratch (device globals; no allocation) ----------------
__device__ float g_nts[NT];
__device__ float g_mts[NT];
__device__ float g_uts[NT];

__device__ float g_names_emb[(size_t)NC*NB*NH];  // 9.8 MB
__device__ float g_nscore[NC*NB];
__device__ float g_name_e[NC*NH];

__device__ float g_memb[(size_t)NM*NH];          // 6.1 MB
__device__ float g_mscore[NM];

__device__ float g_utt_e[NC*NH];
__device__ int   g_has_utt[NC];

// ---------------- block reductions (any blockDim multiple of 32, <=1024) ----------------
__device__ __forceinline__ float blockReduceSum(float v) {
    __shared__ float sh[32];
    __shared__ float res;
    int lane = threadIdx.x & 31, wid = threadIdx.x >> 5, nw = blockDim.x >> 5;
    #pragma unroll
    for (int o = 16; o; o >>= 1) v += __shfl_xor_sync(0xffffffffu, v, o);
    if (lane == 0) sh[wid] = v;
    __syncthreads();
    if (threadIdx.x == 0) {
        float s = 0.f;
        for (int i = 0; i < nw; i++) s += sh[i];
        res = s;
    }
    __syncthreads();
    return res;
}

__device__ __forceinline__ float blockReduceMax(float v) {
    __shared__ float sh[32];
    __shared__ float res;
    int lane = threadIdx.x & 31, wid = threadIdx.x >> 5, nw = blockDim.x >> 5;
    #pragma unroll
    for (int o = 16; o; o >>= 1) v = fmaxf(v, __shfl_xor_sync(0xffffffffu, v, o));
    if (lane == 0) sh[wid] = v;
    __syncthreads();
    if (threadIdx.x == 0) {
        float s = NEGINF;
        for (int i = 0; i < nw; i++) s = fmaxf(s, sh[i]);
        res = s;
    }
    __syncthreads();
    return res;
}

// ---------------- K1: fused token projections (nts, mts, uts) ----------------
__global__ void k_proj(const float* __restrict__ se,
                       const float* __restrict__ w_nt, const float* __restrict__ b_nt,
                       const float* __restrict__ w_mt, const float* __restrict__ b_mt,
                       const float* __restrict__ w_ut, const float* __restrict__ b_ut) {
    int warp = (blockIdx.x * blockDim.x + threadIdx.x) >> 5;
    int lane = threadIdx.x & 31;
    if (warp >= NT) return;
    const float4* row = (const float4*)(se + (size_t)warp * NH);
    const float4* wn = (const float4*)w_nt;
    const float4* wm = (const float4*)w_mt;
    const float4* wu = (const float4*)w_ut;
    float a = 0.f, b = 0.f, c = 0.f;
    #pragma unroll
    for (int i = 0; i < 6; i++) {
        float4 x = row[lane + 32 * i];
        float4 n = __ldg(&wn[lane + 32 * i]);
        float4 m = __ldg(&wm[lane + 32 * i]);
        float4 u = __ldg(&wu[lane + 32 * i]);
        a += x.x*n.x + x.y*n.y + x.z*n.z + x.w*n.w;
        b += x.x*m.x + x.y*m.y + x.z*m.z + x.w*m.w;
        c += x.x*u.x + x.y*u.y + x.z*u.z + x.w*u.w;
    }
    #pragma unroll
    for (int o = 16; o; o >>= 1) {
        a += __shfl_xor_sync(0xffffffffu, a, o);
        b += __shfl_xor_sync(0xffffffffu, b, o);
        c += __shfl_xor_sync(0xffffffffu, c, o);
    }
    if (lane == 0) {
        g_nts[warp] = a + __ldg(b_nt);
        g_mts[warp] = b + __ldg(b_mt);
        g_uts[warp] = c + __ldg(b_ut);
    }
}

// ---------------- K2: per-(char, block) name attention ----------------
__global__ void k_names(const float* __restrict__ se,
                        const float* __restrict__ nmask,
                        const float* __restrict__ w_name, const float* __restrict__ b_name) {
    int c = blockIdx.x / NB, b = blockIdx.x % NB;
    int tid = threadIdx.x;
    __shared__ int s_idx[NS];
    __shared__ float s_w[NS];
    __shared__ int s_cnt;
    if (tid == 0) s_cnt = 0;
    __syncthreads();

    float lmax = NEGINF;
    for (int s = tid; s < NS; s += 256) {
        float m = nmask[c * NS + s];
        if (m > -1e30f) {
            float sc = m + g_nts[b * NS + s];
            int p = atomicAdd(&s_cnt, 1);
            s_idx[p] = s; s_w[p] = sc;
            lmax = fmaxf(lmax, sc);
        }
    }
    lmax = blockReduceMax(lmax);          // barrier makes list writes visible
    int cnt = s_cnt;

    float lsum = 0.f;
    for (int i = tid; i < cnt; i += 256) {
        float e = expf(s_w[i] - lmax);
        s_w[i] = e; lsum += e;
    }
    float tot = blockReduceSum(lsum);
    float inv = 1.f / tot;

    const float* blk = se + (size_t)b * NS * NH;
    float a0 = 0.f, a1 = 0.f, a2 = 0.f;
    int i = 0;
    for (; i + 1 < cnt; i += 2) {
        int sA = s_idx[i], sB = s_idx[i + 1];
        float wA = s_w[i] * inv, wB = s_w[i + 1] * inv;
        const float* rA = blk + (size_t)sA * NH;
        const float* rB = blk + (size_t)sB * NH;
        a0 += wA * rA[tid]       + wB * rB[tid];
        a1 += wA * rA[tid + 256] + wB * rB[tid + 256];
        a2 += wA * rA[tid + 512] + wB * rB[tid + 512];
    }
    if (i < cnt) {
        int s = s_idx[i];
        float w = s_w[i] * inv;
        const float* r = blk + (size_t)s * NH;
        a0 += w * r[tid]; a1 += w * r[tid + 256]; a2 += w * r[tid + 512];
    }
    size_t o = ((size_t)c * NB + b) * NH;
    g_names_emb[o + tid]       = a0;
    g_names_emb[o + tid + 256] = a1;
    g_names_emb[o + tid + 512] = a2;

    float d = a0 * __ldg(&w_name[tid]) + a1 * __ldg(&w_name[tid + 256]) + a2 * __ldg(&w_name[tid + 512]);
    d = blockReduceSum(d);
    if (tid == 0) g_nscore[c * NB + b] = d + __ldg(b_name);
}

// ---------------- K3: name_e = softmax over blocks (1024 thr, 4-way b-split) --------
__global__ void k_name_e() {
    int c = blockIdx.x, tid = threadIdx.x;
    int grp = tid >> 8, gtid = tid & 255;
    __shared__ float p[NB];
    __shared__ float sp[4][NH];
    if (tid == 0) {
        float mx = NEGINF;
        for (int b = 0; b < NB; b++) mx = fmaxf(mx, g_nscore[c * NB + b]);
        float s = 0.f;
        for (int b = 0; b < NB; b++) { float e = expf(g_nscore[c * NB + b] - mx); p[b] = e; s += e; }
        float inv = 1.f / s;
        for (int b = 0; b < NB; b++) p[b] *= inv;
    }
    __syncthreads();
    float a0 = 0.f, a1 = 0.f, a2 = 0.f;
    const float* base = g_names_emb + (size_t)c * NB * NH;
    for (int b = grp; b < NB; b += 4) {
        float w = p[b];
        const float* r = base + (size_t)b * NH;
        a0 += w * r[gtid]; a1 += w * r[gtid + 256]; a2 += w * r[gtid + 512];
    }
    sp[grp][gtid] = a0; sp[grp][gtid + 256] = a1; sp[grp][gtid + 512] = a2;
    __syncthreads();
    if (tid < NH) {
        g_name_e[c * NH + tid] = sp[0][tid] + sp[1][tid] + sp[2][tid] + sp[3][tid];
    }
}

// ---------------- K4: fused mention compaction + softmax + gather + score ----------------
__global__ void k_mention(const float* __restrict__ mmask,
                          const float* __restrict__ se,
                          const float* __restrict__ w_men, const float* __restrict__ b_men) {
    int m = blockIdx.x, tid = threadIdx.x;
    __shared__ int s_idx[MCAP];
    __shared__ float s_sc[MCAP];
    __shared__ int s_cnt;
    if (tid == 0) s_cnt = 0;
    __syncthreads();

    const float4* row = (const float4*)(mmask + (size_t)m * NT);
    float lmax = NEGINF;
    // scan 32768 floats with streaming (evict-first) loads, 4 in flight per thread
    for (int base = tid; base < NT / 4; base += 1024) {
        float4 v0 = __ldcs(row + base);
        float4 v1 = __ldcs(row + base + 256);
        float4 v2 = __ldcs(row + base + 512);
        float4 v3 = __ldcs(row + base + 768);
        #define PROC(v, boff) { \
            int t0 = (base + boff) * 4; \
            if ((v).x > -1e30f) { int p = atomicAdd(&s_cnt, 1); if (p < MCAP) { float sc = (v).x + g_mts[t0];     s_idx[p] = t0;     s_sc[p] = sc; lmax = fmaxf(lmax, sc); } } \
            if ((v).y > -1e30f) { int p = atomicAdd(&s_cnt, 1); if (p < MCAP) { float sc = (v).y + g_mts[t0 + 1]; s_idx[p] = t0 + 1; s_sc[p] = sc; lmax = fmaxf(lmax, sc); } } \
            if ((v).z > -1e30f) { int p = atomicAdd(&s_cnt, 1); if (p < MCAP) { float sc = (v).z + g_mts[t0 + 2]; s_idx[p] = t0 + 2; s_sc[p] = sc; lmax = fmaxf(lmax, sc); } } \
            if ((v).w > -1e30f) { int p = atomicAdd(&s_cnt, 1); if (p < MCAP) { float sc = (v).w + g_mts[t0 + 3]; s_idx[p] = t0 + 3; s_sc[p] = sc; lmax = fmaxf(lmax, sc); } } }
        PROC(v0, 0) PROC(v1, 256) PROC(v2, 512) PROC(v3, 768)
        #undef PROC
    }
    lmax = blockReduceMax(lmax);          // barrier: list complete & visible
    int cnt = min(s_cnt, MCAP);

    float lsum = 0.f;
    for (int i = tid; i < cnt; i += 256) {
        float e = expf(s_sc[i] - lmax);
        s_sc[i] = e; lsum += e;
    }
    float tot = blockReduceSum(lsum);     // barrier: s_sc exp values visible
    float inv = 1.f / tot;

    float a0 = 0.f, a1 = 0.f, a2 = 0.f;
    int i = 0;
    for (; i + 1 < cnt; i += 2) {
        int tA = s_idx[i], tB = s_idx[i + 1];
        float wA = s_sc[i] * inv, wB = s_sc[i + 1] * inv;
        const float* rA = se + (size_t)tA * NH;
        const float* rB = se + (size_t)tB * NH;
        a0 += wA * rA[tid]       + wB * rB[tid];
        a1 += wA * rA[tid + 256] + wB * rB[tid + 256];
        a2 += wA * rA[tid + 512] + wB * rB[tid + 512];
    }
    if (i < cnt) {
        int t = s_idx[i];
        float w = s_sc[i] * inv;
        const float* r = se + (size_t)t * NH;
        a0 += w * r[tid]; a1 += w * r[tid + 256]; a2 += w * r[tid + 512];
    }
    size_t o = (size_t)m * NH;
    g_memb[o + tid]       = a0;
    g_memb[o + tid + 256] = a1;
    g_memb[o + tid + 512] = a2;
    float d = a0 * __ldg(&w_men[tid]) + a1 * __ldg(&w_men[tid + 256]) + a2 * __ldg(&w_men[tid + 512]);
    d = blockReduceSum(d);
    if (tid == 0) g_mscore[m] = d + __ldg(b_men);
}

// ---------------- K5: utterance attention per char (1024 thr, 4-way entry split) ----
__global__ void k_utt(const float* __restrict__ umask, const float* __restrict__ se) {
    int c = blockIdx.x, tid = threadIdx.x;
    int grp = tid >> 8, gtid = tid & 255;
    __shared__ int s_idx[UCAP];
    __shared__ float s_sc[UCAP];
    __shared__ float sp[4][NH];
    __shared__ int s_cnt;
    if (tid == 0) s_cnt = 0;
    __syncthreads();

    const float4* row = (const float4*)(umask + (size_t)c * NT);
    float lmax = NEGINF;
    for (int base = tid; base < NT / 4; base += 2048) {
        float4 v0 = __ldcs(row + base);
        float4 v1 = __ldcs(row + base + 1024);
        #define PROC(v, boff) { \
            int t0 = (base + boff) * 4; \
            if ((v).x > -1e30f) { int p = atomicAdd(&s_cnt, 1); if (p < UCAP) { float sc = (v).x + g_uts[t0];     s_idx[p] = t0;     s_sc[p] = sc; lmax = fmaxf(lmax, sc); } } \
            if ((v).y > -1e30f) { int p = atomicAdd(&s_cnt, 1); if (p < UCAP) { float sc = (v).y + g_uts[t0 + 1]; s_idx[p] = t0 + 1; s_sc[p] = sc; lmax = fmaxf(lmax, sc); } } \
            if ((v).z > -1e30f) { int p = atomicAdd(&s_cnt, 1); if (p < UCAP) { float sc = (v).z + g_uts[t0 + 2]; s_idx[p] = t0 + 2; s_sc[p] = sc; lmax = fmaxf(lmax, sc); } } \
            if ((v).w > -1e30f) { int p = atomicAdd(&s_cnt, 1); if (p < UCAP) { float sc = (v).w + g_uts[t0 + 3]; s_idx[p] = t0 + 3; s_sc[p] = sc; lmax = fmaxf(lmax, sc); } } }
        PROC(v0, 0) PROC(v1, 1024)
        #undef PROC
    }
    lmax = blockReduceMax(lmax);
    int cnt = min(s_cnt, UCAP);

    if (cnt == 0) {  // no utterances: softmax is NaN -> nan_to_num -> zeros
        if (tid < NH) {
            g_utt_e[c * NH + tid] = 0.f;
        }
        if (tid == 0) g_has_utt[c] = 0;
        return;
    }

    float lsum = 0.f;
    for (int i = tid; i < cnt; i += 1024) {
        float e = expf(s_sc[i] - lmax);
        s_sc[i] = e; lsum += e;
    }
    float tot = blockReduceSum(lsum);
    float inv = 1.f / tot;

    float a0 = 0.f, a1 = 0.f, a2 = 0.f;
    for (int i = grp; i < cnt; i += 4) {
        int t = s_idx[i];
        float w = s_sc[i] * inv;
        const float* r = se + (size_t)t * NH;
        a0 += w * r[gtid];
        a1 += w * r[gtid + 256];
        a2 += w * r[gtid + 512];
    }
    sp[grp][gtid] = a0; sp[grp][gtid + 256] = a1; sp[grp][gtid + 512] = a2;
    __syncthreads();
    if (tid < NH) {
        g_utt_e[c * NH + tid] = sp[0][tid] + sp[1][tid] + sp[2][tid] + sp[3][tid];
    }
    if (tid == 0) g_has_utt[c] = 1;
}

// ---------------- K6: fused mention segment softmax + final combine ----------------
__global__ void k_combine(const int* __restrict__ mids,
                          const float* __restrict__ w_comb, const float* __restrict__ b_comb,
                          float* __restrict__ out) {
    int c = blockIdx.x, tid = threadIdx.x;
    __shared__ int s_m[SCAP];
    __shared__ float s_w[SCAP];
    __shared__ int s_cnt;
    if (tid == 0) s_cnt = 0;
    __syncthreads();

    float lmax = NEGINF;
    for (int m = tid; m < NM; m += 256) {
        if (__ldg(&mids[m]) == c) {
            int p = atomicAdd(&s_cnt, 1);
            if (p < SCAP) {
                float sc = g_mscore[m];
                s_m[p] = m; s_w[p] = sc;
                lmax = fmaxf(lmax, sc);
            }
        }
    }
    lmax = blockReduceMax(lmax);
    int cnt = min(s_cnt, SCAP);

    float m0 = 0.f, m1 = 0.f, m2 = 0.f;
    int has_mention = (cnt > 0);
    if (cnt > 0) {
        float lsum = 0.f;
        for (int i = tid; i < cnt; i += 256) {
            float e = expf(s_w[i] - lmax);
            s_w[i] = e; lsum += e;
        }
        float tot = blockReduceSum(lsum);
        float inv = 1.f / tot;
        for (int i = 0; i < cnt; i++) {
            float w = s_w[i] * inv;
            const float* r = g_memb + (size_t)s_m[i] * NH;
            m0 += w * r[tid];
            m1 += w * r[tid + 256];
            m2 += w * r[tid + 512];
        }
    }

    float wc0 = __ldg(&w_comb[tid]), wc1 = __ldg(&w_comb[tid + 256]), wc2 = __ldg(&w_comb[tid + 512]);
    float n0 = g_name_e[c * NH + tid], n1 = g_name_e[c * NH + tid + 256], n2 = g_name_e[c * NH + tid + 512];
    float u0 = g_utt_e[c * NH + tid], u1 = g_utt_e[c * NH + tid + 256], u2 = g_utt_e[c * NH + tid + 512];

    float dn = blockReduceSum(n0 * wc0 + n1 * wc1 + n2 * wc2);
    float dm = blockReduceSum(m0 * wc0 + m1 * wc1 + m2 * wc2);
    float du = blockReduceSum(u0 * wc0 + u1 * wc1 + u2 * wc2);

    __shared__ float attn[3];
    if (tid == 0) {
        float bc = __ldg(b_comb);
        float s0 = dn + bc;
        float s1 = has_mention  ? (dm + bc) : NEGINF;
        float s2 = g_has_utt[c] ? (du + bc) : NEGINF;
        float mx = fmaxf(s0, fmaxf(s1, s2));
        float e0 = expf(s0 - mx);
        float e1 = (s1 > -1e30f) ? expf(s1 - mx) : 0.f;
        float e2 = (s2 > -1e30f) ? expf(s2 - mx) : 0.f;
        float inv = 1.f / (e0 + e1 + e2);
        attn[0] = e0 * inv; attn[1] = e1 * inv; attn[2] = e2 * inv;
    }
    __syncthreads();
    float A0 = attn[0], A1 = attn[1], A2 = attn[2];
    out[c * NH + tid]       = A0 * n0 + A1 * m0 + A2 * u0;
    out[c * NH + tid + 256] = A0 * n1 + A1 * m1 + A2 * u1;
    out[c * NH + tid + 512] = A0 * n2 + A1 * m2 + A2 * u2;
}

// ---------------- launch ----------------
extern "C" void kernel_launch(void* const* d_in, const int* in_sizes, int n_in,
                              void* d_out, int out_size) {
    const float* se        = (const float*)d_in[0];
    const float* nmask     = (const float*)d_in[1];
    const float* umask     = (const float*)d_in[2];
    const float* mmask     = (const float*)d_in[3];
    const int*   mids      = (const int*)  d_in[4];
    const float* w_name_tok = (const float*)d_in[5];
    const float* b_name_tok = (const float*)d_in[6];
    const float* w_name     = (const float*)d_in[7];
    const float* b_name     = (const float*)d_in[8];
    const float* w_men_tok  = (const float*)d_in[9];
    const float* b_men_tok  = (const float*)d_in[10];
    const float* w_men      = (const float*)d_in[11];
    const float* b_men      = (const float*)d_in[12];
    const float* w_utt      = (const float*)d_in[13];
    const float* b_utt      = (const float*)d_in[14];
    const float* w_comb     = (const float*)d_in[15];
    const float* b_comb     = (const float*)d_in[16];
    float* out = (float*)d_out;

    k_proj<<<NT / 8, 256>>>(se, w_name_tok, b_name_tok, w_men_tok, b_men_tok, w_utt, b_utt);
    k_names<<<NC * NB, 256>>>(se, nmask, w_name, b_name);
    k_name_e<<<NC, 1024>>>();
    k_mention<<<NM, 256>>>(mmask, se, w_men, b_men);
    k_utt<<<NC, 1024>>>(umask, se);
    k_combine<<<NC, 256>>>(mids, w_comb, b_comb, out);
}